// round 2
// baseline (speedup 1.0000x reference)
#include <cuda_runtime.h>
#include <cuda_fp16.h>
#include <cstdint>

// ============================================================================
// QATLinear: y[t,o] = scale[o] * sum_i x[t,i]*sign(w[o,i]) + b[o]
//
// sign(W) = +-1 is EXACT in fp16; x rounded to fp16 (rel rms ~2.8e-4) with
// fp32 mma.sync accumulation => output norm-relative error ~3e-4 < 1e-3.
// PTX target is compute_103 (no 'a'), so tcgen05 is unavailable; use the
// register-path mma.sync.m16n8k16 + ldmatrix + cp.async multistage pipeline.
//
// GEMM: D = A(fp16)[M,K] * B(+-1 fp16)[N,K]^T, M=8192 N=16384 K=4096.
// Tiles: BM=128 BN=256 BK=32, 512 threads (4x4 warps, warp tile 32x64),
// 4-stage cp.async, XOR-swizzled smem, GROUP_M tile swizzle, fused epilogue.
// ============================================================================

#define TOKENS 8192
#define DIN    4096
#define DOUT   16384

static constexpr int BM = 128;
static constexpr int BN = 256;
static constexpr int BK = 32;
static constexpr int STAGES = 4;
static constexpr int THREADS = 512;
static constexpr int NCHUNK = DIN / BK;          // 128

static constexpr int A_STAGE_B = BM * BK * 2;    // 8192 B
static constexpr int B_STAGE_B = BN * BK * 2;    // 16384 B
static constexpr int STAGE_B   = A_STAGE_B + B_STAGE_B;   // 24576
static constexpr int SMEM_TOTAL = STAGES * STAGE_B;       // 98304

// ---- scratch (device globals: allocation-free rule) ----
__device__ __half g_A [(size_t)TOKENS * DIN];    // 64 MB  (x as fp16)
__device__ __half g_Bs[(size_t)DOUT  * DIN];     // 128 MB (sign(w) as fp16)

// ============================ PTX helpers ===================================
__device__ __forceinline__ uint32_t smem_u32(const void* p) {
    uint32_t a;
    asm("{ .reg .u64 t; cvta.to.shared.u64 t, %1; cvt.u32.u64 %0, t; }"
        : "=r"(a) : "l"(p));
    return a;
}
__device__ __forceinline__ void cp_async16(uint32_t saddr, const void* gptr) {
    asm volatile("cp.async.cg.shared.global [%0], [%1], 16;"
                 :: "r"(saddr), "l"(gptr) : "memory");
}
__device__ __forceinline__ void cp_commit() {
    asm volatile("cp.async.commit_group;" ::: "memory");
}
template <int N>
__device__ __forceinline__ void cp_wait() {
    asm volatile("cp.async.wait_group %0;" :: "n"(N) : "memory");
}
__device__ __forceinline__ void ldmatrix_x4(uint32_t& r0, uint32_t& r1,
                                            uint32_t& r2, uint32_t& r3,
                                            uint32_t addr) {
    asm volatile("ldmatrix.sync.aligned.m8n8.x4.shared.b16 {%0,%1,%2,%3}, [%4];"
                 : "=r"(r0), "=r"(r1), "=r"(r2), "=r"(r3) : "r"(addr));
}
__device__ __forceinline__ void mma_16816(float* c, const uint32_t* a,
                                          const uint32_t* b) {
    asm volatile(
        "mma.sync.aligned.m16n8k16.row.col.f32.f16.f16.f32 "
        "{%0,%1,%2,%3}, {%4,%5,%6,%7}, {%8,%9}, {%0,%1,%2,%3};"
        : "+f"(c[0]), "+f"(c[1]), "+f"(c[2]), "+f"(c[3])
        : "r"(a[0]), "r"(a[1]), "r"(a[2]), "r"(a[3]), "r"(b[0]), "r"(b[1]));
}
// smem tile layout: rows of BK fp16 = 64 B = 4 x 16B chunks,
// chunk' = chunk ^ ((row>>1)&3)  -> conflict-free ldmatrix & cp.async stores
__device__ __forceinline__ uint32_t sw_off(int row, int chunk) {
    return (uint32_t)(row * 64 + ((chunk ^ ((row >> 1) & 3)) << 4));
}

// ============================ prep kernels ==================================
__global__ void prep_a_kernel(const float* __restrict__ x) {
    size_t i = (size_t)blockIdx.x * blockDim.x + threadIdx.x;
    const size_t n4 = (size_t)TOKENS * DIN / 4;
    if (i >= n4) return;
    float4 v = __ldg((const float4*)x + i);
    uint32_t h0 = __half_as_ushort(__float2half_rn(v.x))
                | ((uint32_t)__half_as_ushort(__float2half_rn(v.y)) << 16);
    uint32_t h1 = __half_as_ushort(__float2half_rn(v.z))
                | ((uint32_t)__half_as_ushort(__float2half_rn(v.w)) << 16);
    uint2 p; p.x = h0; p.y = h1;
    ((uint2*)g_A)[i] = p;
}
__global__ void prep_b_kernel(const float* __restrict__ w) {
    size_t i = (size_t)blockIdx.x * blockDim.x + threadIdx.x;
    const size_t n4 = (size_t)DOUT * DIN / 4;
    if (i >= n4) return;
    float4 v = __ldg((const float4*)w + i);
    // sign with 0 -> +1 ; fp16 +1.0 = 0x3C00, -1.0 = 0xBC00
    uint32_t s0 = (v.x >= 0.0f) ? 0x3C00u : 0xBC00u;
    uint32_t s1 = (v.y >= 0.0f) ? 0x3C00u : 0xBC00u;
    uint32_t s2 = (v.z >= 0.0f) ? 0x3C00u : 0xBC00u;
    uint32_t s3 = (v.w >= 0.0f) ? 0x3C00u : 0xBC00u;
    uint2 p; p.x = s0 | (s1 << 16); p.y = s2 | (s3 << 16);
    ((uint2*)g_Bs)[i] = p;
}

// ============================ GEMM kernel ===================================
__global__ void __launch_bounds__(THREADS, 1)
qat_gemm_kernel(const float* __restrict__ scale, const float* __restrict__ bias,
                float* __restrict__ out) {
    extern __shared__ char smem[];
    const uint32_t sbase = smem_u32(smem);
    const int tid  = threadIdx.x;
    const int wid  = tid >> 5;
    const int lane = tid & 31;

    // grouped tile swizzle (GROUP_M = 8): 64 m-tiles x 64 n-tiles
    const int pid   = blockIdx.x;
    const int group = pid >> 9;               // / (8*64)
    const int inb   = pid & 511;
    const int pid_m = (group << 3) + (inb & 7);
    const int pid_n = inb >> 3;
    const int m0 = pid_m * BM;
    const int n0 = pid_n * BN;

    // warp tile: 32 (m) x 64 (n); warps: 4 (m) x 4 (n)
    const int warp_m = wid & 3;
    const int warp_n = wid >> 2;
    const int wm0 = warp_m * 32;
    const int wn0 = warp_n * 64;

    // ---- global load indices (16B per cp.async) ----
    // A: 128 rows x 4 chunks = 512 -> 1 per thread
    const int a_row = tid >> 2, a_chk = tid & 3;
    // B: 256 rows x 4 chunks = 1024 -> 2 per thread
    const int b_row0 = tid >> 2, b_chk = tid & 3;     // + second: b_row0+128

    const __half* gA = g_A  + (size_t)(m0 + a_row) * DIN + a_chk * 8;
    const __half* gB0 = g_Bs + (size_t)(n0 + b_row0) * DIN + b_chk * 8;
    const __half* gB1 = gB0 + (size_t)128 * DIN;

    const uint32_t sA_off  = sw_off(a_row, a_chk);
    const uint32_t sB_off0 = sw_off(b_row0, b_chk);
    const uint32_t sB_off1 = sw_off(b_row0 + 128, b_chk);

    auto issue_stage = [&](int c) {
        const int s = c % STAGES;
        const uint32_t stA = sbase + s * STAGE_B;
        const uint32_t stB = stA + A_STAGE_B;
        const size_t kofs = (size_t)c * BK;
        cp_async16(stA + sA_off,  gA  + kofs);
        cp_async16(stB + sB_off0, gB0 + kofs);
        cp_async16(stB + sB_off1, gB1 + kofs);
    };

    // ---- prologue: fill STAGES-1 stages ----
#pragma unroll
    for (int c = 0; c < STAGES - 1; ++c) { issue_stage(c); cp_commit(); }

    // ---- accumulators: 2 m-frags x 8 n-frags x 4 ----
    float acc[2][8][4];
#pragma unroll
    for (int i = 0; i < 2; ++i)
#pragma unroll
        for (int j = 0; j < 8; ++j)
#pragma unroll
            for (int q = 0; q < 4; ++q) acc[i][j][q] = 0.0f;

    // ldmatrix lane addressing (precompute row/chunk components)
    const int lquad = lane >> 3;              // 0..3 : which 8x8 matrix
    const int lrow  = lane & 7;

#pragma unroll 1
    for (int c = 0; c < NCHUNK; ++c) {
        cp_wait<STAGES - 2>();
        __syncthreads();

        // issue next stage into the slot freed by chunk c-1
        if (c + STAGES - 1 < NCHUNK) issue_stage(c + STAGES - 1);
        cp_commit();

        const int s = c % STAGES;
        const uint32_t stA = sbase + s * STAGE_B;
        const uint32_t stB = stA + A_STAGE_B;

#pragma unroll
        for (int kh = 0; kh < 2; ++kh) {      // two k16 halves of BK=32
            const int kchunk = kh * 2;        // 16B-chunk index of k16 base

            // A frags: 2 m16 tiles
            uint32_t afr[2][4];
#pragma unroll
            for (int mi = 0; mi < 2; ++mi) {
                // lanes: quad 0: rows m+0..7 @kc, quad1: m+8..15 @kc,
                //        quad2: m+0..7 @kc+1, quad3: m+8..15 @kc+1
                int row = wm0 + mi * 16 + lrow + ((lquad & 1) << 3);
                int chk = kchunk + (lquad >> 1);
                ldmatrix_x4(afr[mi][0], afr[mi][1], afr[mi][2], afr[mi][3],
                            stA + sw_off(row, chk));
            }
            // B frags: 8 n8 tiles, 2 per ldmatrix.x4
            uint32_t bfr[8][2];
#pragma unroll
            for (int jp = 0; jp < 4; ++jp) {
                // lanes: quad0: rows n+0..7 @kc, quad1: n+0..7 @kc+1,
                //        quad2: rows n+8..15 @kc, quad3: @kc+1
                int row = wn0 + jp * 16 + lrow + ((lquad >> 1) << 3);
                int chk = kchunk + (lquad & 1);
                uint32_t r0, r1, r2, r3;
                ldmatrix_x4(r0, r1, r2, r3, stB + sw_off(row, chk));
                bfr[jp * 2 + 0][0] = r0; bfr[jp * 2 + 0][1] = r1;
                bfr[jp * 2 + 1][0] = r2; bfr[jp * 2 + 1][1] = r3;
            }
#pragma unroll
            for (int mi = 0; mi < 2; ++mi)
#pragma unroll
                for (int j = 0; j < 8; ++j)
                    mma_16816(acc[mi][j], afr[mi], bfr[j]);
        }
        __syncthreads();
    }

    // ---- epilogue: fused scale/bias, float2 stores ----
    const int tq = lane >> 2;                 // 0..7 (row within frag)
    const int tr = lane & 3;                  // col pair selector
#pragma unroll
    for (int j = 0; j < 8; ++j) {
        const int n = n0 + wn0 + j * 8 + 2 * tr;
        const float2 sc = *(const float2*)(scale + n);
        const float2 bb = *(const float2*)(bias + n);
#pragma unroll
        for (int mi = 0; mi < 2; ++mi) {
            const int mrow = m0 + wm0 + mi * 16 + tq;
            float2 v0, v1;
            v0.x = fmaf(sc.x, acc[mi][j][0], bb.x);
            v0.y = fmaf(sc.y, acc[mi][j][1], bb.y);
            v1.x = fmaf(sc.x, acc[mi][j][2], bb.x);
            v1.y = fmaf(sc.y, acc[mi][j][3], bb.y);
            *(float2*)(out + (size_t)mrow * DOUT + n) = v0;
            *(float2*)(out + (size_t)(mrow + 8) * DOUT + n) = v1;
        }
    }
}

// ============================ launch ========================================
extern "C" void kernel_launch(void* const* d_in, const int* in_sizes, int n_in,
                              void* d_out, int out_size) {
    (void)in_sizes; (void)n_in; (void)out_size;
    const float* x     = (const float*)d_in[0];
    const float* w     = (const float*)d_in[1];
    const float* scale = (const float*)d_in[2];
    const float* b     = (const float*)d_in[3];
    float* out = (float*)d_out;

    {
        size_t n4 = (size_t)TOKENS * DIN / 4;
        prep_a_kernel<<<(unsigned)((n4 + 255) / 256), 256>>>(x);
    }
    {
        size_t n4 = (size_t)DOUT * DIN / 4;
        prep_b_kernel<<<(unsigned)((n4 + 255) / 256), 256>>>(w);
    }

    static bool attr_set = false;
    if (!attr_set) {
        cudaFuncSetAttribute(qat_gemm_kernel,
                             cudaFuncAttributeMaxDynamicSharedMemorySize,
                             SMEM_TOTAL);
        attr_set = true;
    }
    const int grid = (TOKENS / BM) * (DOUT / BN);   // 64 * 64 = 4096
    qat_gemm_kernel<<<grid, THREADS, SMEM_TOTAL>>>(scale, b, out);
}